// round 3
// baseline (speedup 1.0000x reference)
#include <cuda_runtime.h>
#include <cstdint>

#define L2E 1.4426950408889634f
#define BATCH 64
#define SEQ 512
#define HID 768
#define NC 21
#define EM_STRIDE (SEQ * NC)   // 10752 floats per batch

// Scratch. __align__(16): g_em2 is read with float4 (LDG.128).
__device__ __align__(16) float g_em2[BATCH * SEQ * NC];
__device__ float g_res[BATCH];              // per-batch (logZ2 - num2)

__device__ __forceinline__ float fast_ex2(float x) {
    float y; asm("ex2.approx.ftz.f32 %0, %1;" : "=f"(y) : "f"(x)); return y;
}
__device__ __forceinline__ float fast_lg2(float x) {
    float y; asm("lg2.approx.ftz.f32 %0, %1;" : "=f"(y) : "f"(x)); return y;
}

// ---------------------------------------------------------------------------
// Kernel 1: emissions GEMM  em2[b,t,c] = (hidden[b,t,:] @ W[:,c] + b[c]) * log2e
// ---------------------------------------------------------------------------
__global__ __launch_bounds__(256) void gemm_kernel(
    const float* __restrict__ hidden,
    const float* __restrict__ W,
    const float* __restrict__ bias)
{
    __shared__ __align__(16) float hs[128][33];   // +pad: conflict-free
    __shared__ __align__(16) float ws[32][24];    // c padded to 24 for float4

    int tid  = threadIdx.x;
    int m    = tid & 127;
    int half = tid >> 7;
    int row0 = blockIdx.x * 128;

    if (tid < 96) ws[tid / 3][21 + (tid % 3)] = 0.f;

    float acc[12];
#pragma unroll
    for (int i = 0; i < 12; i++) acc[i] = 0.f;

    for (int k0 = 0; k0 < HID; k0 += 32) {
        for (int idx = tid; idx < 32 * NC; idx += 256) {
            int kk = idx / NC;
            int c  = idx - kk * NC;
            ws[kk][c] = W[(k0 + kk) * NC + c];
        }
        for (int idx = tid; idx < 128 * 32; idx += 256) {
            int r  = idx >> 5;
            int kk = idx & 31;
            hs[r][kk] = hidden[(row0 + r) * HID + k0 + kk];
        }
        __syncthreads();
#pragma unroll
        for (int kk = 0; kk < 32; kk++) {
            float h = hs[m][kk];
            const float4* wp = reinterpret_cast<const float4*>(&ws[kk][half * 12]);
            float4 w0 = wp[0], w1 = wp[1], w2 = wp[2];
            acc[0]  += h * w0.x;  acc[1]  += h * w0.y;
            acc[2]  += h * w0.z;  acc[3]  += h * w0.w;
            acc[4]  += h * w1.x;  acc[5]  += h * w1.y;
            acc[6]  += h * w1.z;  acc[7]  += h * w1.w;
            acc[8]  += h * w2.x;  acc[9]  += h * w2.y;
            acc[10] += h * w2.z;  acc[11] += h * w2.w;
        }
        __syncthreads();
    }

    int cb = half * 12;
    int out_base = (row0 + m) * NC;
#pragma unroll
    for (int cc = 0; cc < 12; cc++) {
        int c = cb + cc;
        if (c < NC) g_em2[out_base + c] = (acc[cc] + bias[c]) * L2E;
    }
}

// ---------------------------------------------------------------------------
// Kernel 2: per-batch CRF. Block = 1 batch, 128 threads.
// labels buffer dtype is detected at runtime (int32 vs int64): under default
// JAX config the reference's astype(int64) silently yields int32. Detection
// inspects batch-0's first 1024 int32 words (always in-bounds for both
// dtypes): for genuine int64 data every odd word is a sign word in {0,-1}.
// ---------------------------------------------------------------------------
__global__ __launch_bounds__(128) void crf_kernel(
    const float* __restrict__ start_t,
    const float* __restrict__ end_t,
    const float* __restrict__ trans,
    const int*   __restrict__ labr)      // raw label words
{
    __shared__ __align__(16) float em_s[SEQ * NC];  // 43008 B
    __shared__ float red_f[128];
    __shared__ int   red_i[128];
    __shared__ float s_num2;
    __shared__ int   s_len;

    int b   = blockIdx.x;
    int tid = threadIdx.x;
    const float* em_g = g_em2 + b * EM_STRIDE;

    // ---- dtype detection (bounds-safe: indices <= 1023) ----
    int ok = 1;
    for (int t = tid; t < SEQ; t += 128) {
        int v = labr[2 * t + 1];
        if (v != 0 && v != -1) ok = 0;
    }
    int is64 = __syncthreads_and(ok);
    // low word of little-endian int64 == the value for small ints (incl. -100)
    const int lbase = is64 ? b * SEQ * 2 : b * SEQ;
    const int lstep = is64 ? 2 : 1;
#define LAB(t) labr[lbase + (t) * lstep]

    // stage emissions (already log2-scaled) into smem: 2688 float4s
    for (int i = tid; i < (SEQ * NC) / 4; i += 128)
        reinterpret_cast<float4*>(em_s)[i] =
            reinterpret_cast<const float4*>(em_g)[i];

    // numerator (log2-scaled) + valid length. mask is a prefix: t < len.
    float p = 0.f;
    int cnt = 0;
    for (int t = tid; t < SEQ; t += 128) {
        int l = LAB(t);
        if (l != -100) {
            cnt++;
            if (t == 0) {
                p += start_t[l] * L2E + em_g[l];
            } else {
                int lp = LAB(t - 1);
                p += em_g[t * NC + l] + trans[lp * NC + l] * L2E;
            }
        }
    }
    red_f[tid] = p;
    red_i[tid] = cnt;
    __syncthreads();
    for (int s = 64; s > 0; s >>= 1) {
        if (tid < s) { red_f[tid] += red_f[tid + s]; red_i[tid] += red_i[tid + s]; }
        __syncthreads();
    }
    if (tid == 0) {
        int len = red_i[0];
        s_len   = len;
        s_num2  = red_f[0] + end_t[LAB(len - 1)] * L2E;
    }
    __syncthreads();

    // ---- forward scan: warp 0 only ----
    if (tid < 32) {
        int j = tid < NC ? tid : NC - 1;   // lanes 21..31 mirror lane 20 (never read)
        float t2[NC];
#pragma unroll
        for (int i = 0; i < NC; i++) t2[i] = trans[i * NC + j] * L2E;
        float e2   = end_t[j] * L2E;
        float beta = start_t[j] * L2E + em_s[j];
        float off  = 0.f;
        int   len  = s_len;

        for (int t = 1; t < len; t++) {
            float b0 = __shfl_sync(0xffffffffu, beta, 0);
            off += b0;
            float bl = beta - b0;
            float s0 = 0.f, s1 = 0.f, s2 = 0.f;
#pragma unroll
            for (int i = 0; i < NC; i += 3) {
                float x0 = __shfl_sync(0xffffffffu, bl, i)     + t2[i];
                float x1 = __shfl_sync(0xffffffffu, bl, i + 1) + t2[i + 1];
                float x2 = __shfl_sync(0xffffffffu, bl, i + 2) + t2[i + 2];
                s0 += fast_ex2(x0);
                s1 += fast_ex2(x1);
                s2 += fast_ex2(x2);
            }
            beta = fast_lg2(s0 + s1 + s2) + em_s[t * NC + j];
        }

        // logZ2 = off + lse2(beta + end2)
        float v  = beta + e2;
        float r  = __shfl_sync(0xffffffffu, v, 0);
        float ex = (tid < NC) ? fast_ex2(v - r) : 0.f;
#pragma unroll
        for (int d = 16; d > 0; d >>= 1)
            ex += __shfl_xor_sync(0xffffffffu, ex, d);
        if (tid == 0)
            g_res[b] = off + r + fast_lg2(ex) - s_num2;
    }
#undef LAB
}

// ---------------------------------------------------------------------------
// Kernel 3: deterministic final reduction -> loss = mean(logZ - num)
// ---------------------------------------------------------------------------
__global__ void finish_kernel(float* __restrict__ out) {
    int tid = threadIdx.x;           // 32 threads
    float v = g_res[tid] + g_res[tid + 32];
#pragma unroll
    for (int d = 16; d > 0; d >>= 1)
        v += __shfl_xor_sync(0xffffffffu, v, d);
    if (tid == 0) out[0] = v * (1.0f / (64.0f * L2E));
}

// ---------------------------------------------------------------------------
// Size-based input resolution: element counts are unique except the three
// 21-element vectors, taken in encounter order as (bias, start, end).
// ---------------------------------------------------------------------------
extern "C" void kernel_launch(void* const* d_in, const int* in_sizes, int n_in,
                              void* d_out, int out_size)
{
    const float* hidden = nullptr;
    const float* W      = nullptr;
    const float* trans  = nullptr;
    const int*   labels = nullptr;
    const float* small[3] = {nullptr, nullptr, nullptr};
    int nsmall = 0;

    for (int i = 0; i < n_in; i++) {
        switch (in_sizes[i]) {
            case BATCH * SEQ * HID: hidden = (const float*)d_in[i]; break;
            case HID * NC:          W      = (const float*)d_in[i]; break;
            case NC * NC:           trans  = (const float*)d_in[i]; break;
            case BATCH * SEQ:       labels = (const int*)d_in[i];   break;
            case NC: if (nsmall < 3) small[nsmall++] = (const float*)d_in[i]; break;
            default: break;
        }
    }
    const float* bias    = small[0];
    const float* start_t = small[1];
    const float* end_t   = small[2];

    gemm_kernel<<<256, 256>>>(hidden, W, bias);
    crf_kernel<<<BATCH, 128>>>(start_t, end_t, trans, labels);
    finish_kernel<<<1, 32>>>((float*)d_out);
}

// round 4
// speedup vs baseline: 1.6827x; 1.6827x over previous
#include <cuda_runtime.h>
#include <cstdint>

#define L2E 1.4426950408889634f
#define BATCH 64
#define SEQ 512
#define HID 768
#define NC 21
#define EM_STRIDE (SEQ * NC)   // 10752 floats per batch

// Scratch. __align__(16): read with float4 (LDG.128).
__device__ __align__(16) float g_em2[BATCH * SEQ * NC];  // log2-scaled emissions
__device__ __align__(16) float g_emx[BATCH * SEQ * NC];  // 2^em2 (linear)
__device__ float g_res[BATCH];                           // per-batch (logZ2 - num2)

__device__ __forceinline__ float fast_ex2(float x) {
    float y; asm("ex2.approx.ftz.f32 %0, %1;" : "=f"(y) : "f"(x)); return y;
}
__device__ __forceinline__ float fast_lg2(float x) {
    float y; asm("lg2.approx.ftz.f32 %0, %1;" : "=f"(y) : "f"(x)); return y;
}
__device__ __forceinline__ void cp_async4(void* smem_dst, const void* gmem_src) {
    unsigned d = (unsigned)__cvta_generic_to_shared(smem_dst);
    asm volatile("cp.async.ca.shared.global [%0], [%1], 4;" :: "r"(d), "l"(gmem_src));
}
__device__ __forceinline__ void cp_commit() {
    asm volatile("cp.async.commit_group;");
}

// ---------------------------------------------------------------------------
// Kernel 1: emissions GEMM, 3-stage cp.async pipeline.
// 512 blocks x 128 threads, BM=64 rows/block, BK=32.
// thread = (m = tid&63, half = tid>>6); half covers c in [half*12, half*12+12).
// ---------------------------------------------------------------------------
__global__ __launch_bounds__(128) void gemm_kernel(
    const float* __restrict__ hidden,
    const float* __restrict__ W,
    const float* __restrict__ bias)
{
    __shared__ __align__(16) float hs[3][64][33];   // 64x32 tile, +1 pad
    __shared__ __align__(16) float ws[3][32][24];   // 32x21, pad to 24 for float4

    const int tid  = threadIdx.x;
    const int m    = tid & 63;
    const int half = tid >> 6;
    const int row0 = blockIdx.x * 64;

    // zero the 3 pad columns of every ws row once (half=1 FFMAs read them)
    for (int i = tid; i < 3 * 32 * 3; i += 128) {
        int s = i / 96, rem = i % 96;
        ws[s][rem / 3][21 + rem % 3] = 0.f;
    }

    auto issue = [&](int k0, int s) {
        // hs: 64*32 = 2048 floats / 128 threads = 16 per thread, coalesced
#pragma unroll
        for (int u = 0; u < 16; u++) {
            int idx = tid + u * 128;
            int r = idx >> 5, kk = idx & 31;
            cp_async4(&hs[s][r][kk], &hidden[(row0 + r) * HID + k0 + kk]);
        }
        // ws: 32*21 = 672 floats
#pragma unroll
        for (int u = 0; u < 6; u++) {
            int idx = tid + u * 128;
            if (idx < 32 * NC) {
                int kk = idx / NC, c = idx - kk * NC;
                cp_async4(&ws[s][kk][c], &W[(k0 + kk) * NC + c]);
            }
        }
    };

    float acc[12];
#pragma unroll
    for (int i = 0; i < 12; i++) acc[i] = 0.f;

    issue(0, 0);  cp_commit();
    issue(32, 1); cp_commit();

    const int NK = HID / 32;   // 24
    for (int k = 0; k < NK; k++) {
        if (k < NK - 2) asm volatile("cp.async.wait_group 1;");
        else            asm volatile("cp.async.wait_group 0;");
        __syncthreads();

        if (k + 2 < NK) { issue((k + 2) * 32, (k + 2) % 3); cp_commit(); }

        const int s = k % 3;
#pragma unroll
        for (int kk = 0; kk < 32; kk++) {
            float h = hs[s][m][kk];
            const float4* wp = reinterpret_cast<const float4*>(&ws[s][kk][half * 12]);
            float4 w0 = wp[0], w1 = wp[1], w2 = wp[2];
            acc[0]  += h * w0.x;  acc[1]  += h * w0.y;
            acc[2]  += h * w0.z;  acc[3]  += h * w0.w;
            acc[4]  += h * w1.x;  acc[5]  += h * w1.y;
            acc[6]  += h * w1.z;  acc[7]  += h * w1.w;
            acc[8]  += h * w2.x;  acc[9]  += h * w2.y;
            acc[10] += h * w2.z;  acc[11] += h * w2.w;
        }
        // no trailing barrier needed: next iter's wait+syncthreads orders the
        // overwrite of buffer (k-1)%3 (= (k+2)%3 issued next iter) after all
        // threads finish this compute.
        __syncthreads();
    }

    const int cb = half * 12;
    const int out_base = (row0 + m) * NC;
#pragma unroll
    for (int cc = 0; cc < 12; cc++) {
        int c = cb + cc;
        if (c < NC) {
            float v = (acc[cc] + bias[c]) * L2E;
            g_em2[out_base + c] = v;
            g_emx[out_base + c] = fast_ex2(v);
        }
    }
}

// ---------------------------------------------------------------------------
// Kernel 2: per-batch CRF, linear-space forward scan (no MUFU in the loop).
// Block = 1 batch, 128 threads. labels dtype (int32 vs int64) detected at
// runtime: under default JAX x64-disabled config astype(int64) yields int32.
// Detection reads batch-0's first 1024 words (in-bounds for both dtypes).
// ---------------------------------------------------------------------------
__global__ __launch_bounds__(128) void crf_kernel(
    const float* __restrict__ start_t,
    const float* __restrict__ end_t,
    const float* __restrict__ trans,
    const int*   __restrict__ labr)
{
    __shared__ __align__(16) float emx_s[SEQ * NC];  // 43008 B (linear emissions)
    __shared__ float red_f[128];
    __shared__ int   red_i[128];
    __shared__ float s_num2;
    __shared__ int   s_len;

    const int b   = blockIdx.x;
    const int tid = threadIdx.x;
    const float* em_g  = g_em2 + b * EM_STRIDE;
    const float* emx_g = g_emx + b * EM_STRIDE;

    // ---- dtype detection ----
    int ok = 1;
    for (int t = tid; t < SEQ; t += 128) {
        int v = labr[2 * t + 1];
        if (v != 0 && v != -1) ok = 0;
    }
    int is64 = __syncthreads_and(ok);
    const int lbase = is64 ? b * SEQ * 2 : b * SEQ;
    const int lstep = is64 ? 2 : 1;
#define LAB(t) labr[lbase + (t) * lstep]

    // stage linear emissions into smem
    for (int i = tid; i < (SEQ * NC) / 4; i += 128)
        reinterpret_cast<float4*>(emx_s)[i] =
            reinterpret_cast<const float4*>(emx_g)[i];

    // numerator (log2 domain) + valid length (mask is a prefix)
    float p = 0.f;
    int cnt = 0;
    for (int t = tid; t < SEQ; t += 128) {
        int l = LAB(t);
        if (l != -100) {
            cnt++;
            if (t == 0) {
                p += start_t[l] * L2E + em_g[l];
            } else {
                int lp = LAB(t - 1);
                p += em_g[t * NC + l] + trans[lp * NC + l] * L2E;
            }
        }
    }
    red_f[tid] = p;
    red_i[tid] = cnt;
    __syncthreads();
    for (int s = 64; s > 0; s >>= 1) {
        if (tid < s) { red_f[tid] += red_f[tid + s]; red_i[tid] += red_i[tid + s]; }
        __syncthreads();
    }
    if (tid == 0) {
        int len = red_i[0];
        s_len   = len;
        s_num2  = red_f[0] + end_t[LAB(len - 1)] * L2E;
    }
    __syncthreads();

    // ---- forward scan: warp 0, linear space ----
    // Invariant: true alpha2_j(t) = log2(a_j) + offe. Per step:
    //   s_j = sum_i a_i * T_ij   (T = 2^(trans*log2e), constant)
    //   a'_j = s_j * 2^-e * emx_j(t),  e = exponent(a_0)  [exact pow-2 renorm]
    if (tid < 32) {
        const int j = tid < NC ? tid : NC - 1;  // lanes 21..31 mirror lane 20
        float tl[NC];
#pragma unroll
        for (int i = 0; i < NC; i++) tl[i] = fast_ex2(trans[i * NC + j] * L2E);
        const float endx = fast_ex2(end_t[j] * L2E);

        float a    = fast_ex2(start_t[j] * L2E) * emx_s[j];
        int   offe = 0;
        const int len = s_len;

        for (int t = 1; t < len; t++) {
            float emn = emx_s[t * NC + j];          // prefetch early
            float a0  = __shfl_sync(0xffffffffu, a, 0);
            int   e   = ((__float_as_int(a0) >> 23) & 255) - 127;
            float scl = __int_as_float((127 - e) << 23);  // 2^-e (ALU only)
            offe += e;
            float s0 = 0.f, s1 = 0.f, s2 = 0.f;
#pragma unroll
            for (int i = 0; i < NC; i += 3) {
                s0 += __shfl_sync(0xffffffffu, a, i)     * tl[i];
                s1 += __shfl_sync(0xffffffffu, a, i + 1) * tl[i + 1];
                s2 += __shfl_sync(0xffffffffu, a, i + 2) * tl[i + 2];
            }
            a = ((s0 + s1 + s2) * scl) * emn;
        }

        // logZ2 = offe + log2(sum_j a_j * endx_j)
        float ex = (tid < NC) ? a * endx : 0.f;
#pragma unroll
        for (int d = 16; d > 0; d >>= 1)
            ex += __shfl_xor_sync(0xffffffffu, ex, d);
        if (tid == 0)
            g_res[b] = (float)offe + fast_lg2(ex) - s_num2;
    }
#undef LAB
}

// ---------------------------------------------------------------------------
// Kernel 3: deterministic final reduction -> loss = mean(logZ - num)
// ---------------------------------------------------------------------------
__global__ void finish_kernel(float* __restrict__ out) {
    int tid = threadIdx.x;           // 32 threads
    float v = g_res[tid] + g_res[tid + 32];
#pragma unroll
    for (int d = 16; d > 0; d >>= 1)
        v += __shfl_xor_sync(0xffffffffu, v, d);
    if (tid == 0) out[0] = v * (1.0f / (64.0f * L2E));
}

// ---------------------------------------------------------------------------
// Size-based input resolution; the three 21-vectors in encounter order are
// (bias, start, end).
// ---------------------------------------------------------------------------
extern "C" void kernel_launch(void* const* d_in, const int* in_sizes, int n_in,
                              void* d_out, int out_size)
{
    const float* hidden = nullptr;
    const float* W      = nullptr;
    const float* trans  = nullptr;
    const int*   labels = nullptr;
    const float* small[3] = {nullptr, nullptr, nullptr};
    int nsmall = 0;

    for (int i = 0; i < n_in; i++) {
        switch (in_sizes[i]) {
            case BATCH * SEQ * HID: hidden = (const float*)d_in[i]; break;
            case HID * NC:          W      = (const float*)d_in[i]; break;
            case NC * NC:           trans  = (const float*)d_in[i]; break;
            case BATCH * SEQ:       labels = (const int*)d_in[i];   break;
            case NC: if (nsmall < 3) small[nsmall++] = (const float*)d_in[i]; break;
            default: break;
        }
    }
    const float* bias    = small[0];
    const float* start_t = small[1];
    const float* end_t   = small[2];

    gemm_kernel<<<512, 128>>>(hidden, W, bias);
    crf_kernel<<<BATCH, 128>>>(start_t, end_t, trans, labels);
    finish_kernel<<<1, 32>>>((float*)d_out);
}

// round 5
// speedup vs baseline: 1.8414x; 1.0943x over previous
#include <cuda_runtime.h>
#include <cstdint>

#define L2E 1.4426950408889634f
#define BATCH 64
#define SEQ 512
#define HID 768
#define NC 21
#define EM_STRIDE (SEQ * NC)   // 10752 floats per batch

__device__ __align__(16) float g_em2[BATCH * SEQ * NC];  // log2-scaled emissions
__device__ __align__(16) float g_emx[BATCH * SEQ * NC];  // 2^em2 (linear)
__device__ float g_res[BATCH];                           // per-batch (logZ2 - num2)

__device__ __forceinline__ float fast_ex2(float x) {
    float y; asm("ex2.approx.ftz.f32 %0, %1;" : "=f"(y) : "f"(x)); return y;
}
__device__ __forceinline__ float fast_lg2(float x) {
    float y; asm("lg2.approx.ftz.f32 %0, %1;" : "=f"(y) : "f"(x)); return y;
}
__device__ __forceinline__ void cp_async4(void* smem_dst, const void* gmem_src) {
    unsigned d = (unsigned)__cvta_generic_to_shared(smem_dst);
    asm volatile("cp.async.ca.shared.global [%0], [%1], 4;" :: "r"(d), "l"(gmem_src));
}
__device__ __forceinline__ void cp_commit() {
    asm volatile("cp.async.commit_group;");
}
// Packed fp32x2 FMA (sm_103a; PTX-only, doubles FLOPs per issue slot)
#define FFMA2(acc, a, b) \
    asm("fma.rn.f32x2 %0, %1, %2, %3;" : "=l"(acc) : "l"(a), "l"(b), "l"(acc))

// ---------------------------------------------------------------------------
// Kernel 1: emissions GEMM, 3-stage cp.async pipeline + f32x2 + K-split.
// 512 blocks x 256 threads, BM=64, BK=32.
// thread = (m = tid&63, half = (tid>>6)&1 -> 12 cols, ks = tid>>7 -> 16 of 32 kk)
// K-split partials merged through smem at the epilogue.
// ---------------------------------------------------------------------------
__global__ __launch_bounds__(256) void gemm_kernel(
    const float* __restrict__ hidden,
    const float* __restrict__ W,
    const float* __restrict__ bias)
{
    __shared__ __align__(16) float hs[3][64][33];        // 64x32 tile, +1 pad
    __shared__ __align__(16) float ws[3][32][24];        // 32x21, pad->24
    __shared__ __align__(16) uint64_t mrg[64][2][6];     // k-split merge (6 KB)

    const int tid  = threadIdx.x;
    const int m    = tid & 63;
    const int half = (tid >> 6) & 1;
    const int ks   = tid >> 7;
    const int row0 = blockIdx.x * 64;

    // zero ws pad columns (cols 21..23 hit by half==1 FFMA2 lanes)
    for (int i = tid; i < 3 * 32 * 3; i += 256) {
        int s = i / 96, rem = i % 96;
        ws[s][rem / 3][21 + rem % 3] = 0.f;
    }

    auto issue = [&](int k0, int s) {
#pragma unroll
        for (int u = 0; u < 8; u++) {                 // 2048 floats / 256 thr
            int idx = tid + u * 256;
            int r = idx >> 5, kk = idx & 31;
            cp_async4(&hs[s][r][kk], &hidden[(row0 + r) * HID + k0 + kk]);
        }
#pragma unroll
        for (int u = 0; u < 3; u++) {                 // 672 floats
            int idx = tid + u * 256;
            if (idx < 32 * NC) {
                int kk = idx / NC, c = idx - kk * NC;
                cp_async4(&ws[s][kk][c], &W[(k0 + kk) * NC + c]);
            }
        }
    };

    uint64_t acc[6];
#pragma unroll
    for (int i = 0; i < 6; i++) acc[i] = 0ull;

    issue(0, 0);  cp_commit();
    issue(32, 1); cp_commit();

    const int NK = HID / 32;   // 24
    const int kklo = ks * 16;
    for (int k = 0; k < NK; k++) {
        if (k < NK - 2) asm volatile("cp.async.wait_group 1;");
        else            asm volatile("cp.async.wait_group 0;");
        __syncthreads();

        if (k + 2 < NK) { issue((k + 2) * 32, (k + 2) % 3); cp_commit(); }

        const int s = k % 3;
#pragma unroll
        for (int kk = kklo; kk < kklo + 16; kk++) {
            float h = hs[s][m][kk];
            uint64_t h2; asm("mov.b64 %0, {%1, %1};" : "=l"(h2) : "f"(h));
            const ulonglong2* wp =
                reinterpret_cast<const ulonglong2*>(&ws[s][kk][half * 12]);
            ulonglong2 q0 = wp[0], q1 = wp[1], q2 = wp[2];
            FFMA2(acc[0], h2, q0.x); FFMA2(acc[1], h2, q0.y);
            FFMA2(acc[2], h2, q1.x); FFMA2(acc[3], h2, q1.y);
            FFMA2(acc[4], h2, q2.x); FFMA2(acc[5], h2, q2.y);
        }
        __syncthreads();
    }

    // merge k-split partials, apply bias, write em2 + emx
    if (ks == 1) {
#pragma unroll
        for (int i = 0; i < 6; i++) mrg[m][half][i] = acc[i];
    }
    __syncthreads();
    if (ks == 0) {
        const int cb = half * 12;
        const int out_base = (row0 + m) * NC;
#pragma unroll
        for (int p = 0; p < 6; p++) {
            uint64_t o = mrg[m][half][p], sum;
            asm("add.rn.f32x2 %0, %1, %2;" : "=l"(sum) : "l"(acc[p]), "l"(o));
            float2 f = *reinterpret_cast<float2*>(&sum);
            int c = cb + 2 * p;
            if (c < NC) {
                float v = (f.x + bias[c]) * L2E;
                g_em2[out_base + c] = v;
                g_emx[out_base + c] = fast_ex2(v);
            }
            if (c + 1 < NC) {
                float v = (f.y + bias[c + 1]) * L2E;
                g_em2[out_base + c + 1] = v;
                g_emx[out_base + c + 1] = fast_ex2(v);
            }
        }
    }
}

// ---------------------------------------------------------------------------
// Kernel 2: per-batch CRF, linear-space scan with smem-broadcast alpha.
// Block = 1 batch, 128 threads. Per step the alpha vector lives in a
// double-buffered 24-float smem slot: each lane STS's its own a_j, syncwarp,
// then every lane reads all 24 via 6 broadcast LDS.128 (~39 cyc vs ~106 for a
// 21-shuffle chain). Renorm is an exact power of two from v0.x's exponent.
// ---------------------------------------------------------------------------
__global__ __launch_bounds__(128) void crf_kernel(
    const float* __restrict__ start_t,
    const float* __restrict__ end_t,
    const float* __restrict__ trans,
    const int*   __restrict__ labr)
{
    __shared__ __align__(16) float emx_s[SEQ * NC];  // 43008 B
    __shared__ __align__(16) float av[2][24];        // double-buffered alpha
    __shared__ float red_f[128];
    __shared__ int   red_i[128];
    __shared__ float s_num2;
    __shared__ int   s_len;

    const int b   = blockIdx.x;
    const int tid = threadIdx.x;
    const float* em_g  = g_em2 + b * EM_STRIDE;
    const float* emx_g = g_emx + b * EM_STRIDE;

    // ---- labels dtype detection (int32 vs int64; in-bounds for both) ----
    int ok = 1;
    for (int t = tid; t < SEQ; t += 128) {
        int v = labr[2 * t + 1];
        if (v != 0 && v != -1) ok = 0;
    }
    int is64 = __syncthreads_and(ok);
    const int lbase = is64 ? b * SEQ * 2 : b * SEQ;
    const int lstep = is64 ? 2 : 1;
#define LAB(t) labr[lbase + (t) * lstep]

    for (int i = tid; i < (SEQ * NC) / 4; i += 128)
        reinterpret_cast<float4*>(emx_s)[i] =
            reinterpret_cast<const float4*>(emx_g)[i];

    // numerator (log2 domain) + valid length (mask is a prefix)
    float p = 0.f;
    int cnt = 0;
    for (int t = tid; t < SEQ; t += 128) {
        int l = LAB(t);
        if (l != -100) {
            cnt++;
            if (t == 0) {
                p += start_t[l] * L2E + em_g[l];
            } else {
                int lp = LAB(t - 1);
                p += em_g[t * NC + l] + trans[lp * NC + l] * L2E;
            }
        }
    }
    red_f[tid] = p;
    red_i[tid] = cnt;
    __syncthreads();
    for (int s = 64; s > 0; s >>= 1) {
        if (tid < s) { red_f[tid] += red_f[tid + s]; red_i[tid] += red_i[tid + s]; }
        __syncthreads();
    }
    if (tid == 0) {
        int len = red_i[0];
        s_len   = len;
        s_num2  = red_f[0] + end_t[LAB(len - 1)] * L2E;
    }
    __syncthreads();

    // ---- forward scan: warp 0 ----
    if (tid < 32) {
        const int lane = tid;
        const int j = lane < NC ? lane : NC - 1;   // mirror lanes stay finite
        float tl[24];
#pragma unroll
        for (int i = 0; i < NC; i++) tl[i] = fast_ex2(trans[i * NC + j] * L2E);
        tl[21] = tl[22] = tl[23] = 0.f;            // pad coeffs kill pad slots
        const float endx = fast_ex2(end_t[j] * L2E);

        float a = fast_ex2(start_t[j] * L2E) * emx_s[j];
        if (lane < NC)  av[0][lane] = a;
        if (lane >= NC && lane < 24) { av[0][lane] = 0.f; av[1][lane] = 0.f; }
        int offe = 0;
        int buf  = 0;
        const int len = s_len;

        for (int t = 1; t < len; t++) {
            __syncwarp();   // publish av[buf] writes from previous step
            const float4* vp = reinterpret_cast<const float4*>(av[buf]);
            float4 v0 = vp[0], v1 = vp[1], v2 = vp[2],
                   v3 = vp[3], v4 = vp[4], v5 = vp[5];
            float emn = emx_s[t * NC + j];
            int   e   = ((__float_as_int(v0.x) >> 23) & 255) - 127;
            float scl = __int_as_float((127 - e) << 23);   // exact 2^-e
            offe += e;

            float sA = v0.x * tl[0], sB = v0.y * tl[1], sC = v0.z * tl[2];
            sA += v0.w * tl[3];  sB += v1.x * tl[4];  sC += v1.y * tl[5];
            sA += v1.z * tl[6];  sB += v1.w * tl[7];  sC += v2.x * tl[8];
            sA += v2.y * tl[9];  sB += v2.z * tl[10]; sC += v2.w * tl[11];
            sA += v3.x * tl[12]; sB += v3.y * tl[13]; sC += v3.z * tl[14];
            sA += v3.w * tl[15]; sB += v4.x * tl[16]; sC += v4.y * tl[17];
            sA += v4.z * tl[18]; sB += v4.w * tl[19]; sC += v5.x * tl[20];
            sA += v5.y * tl[21]; sB += v5.z * tl[22]; sC += v5.w * tl[23];

            a = (((sA + sB) + sC) * scl) * emn;
            buf ^= 1;
            if (lane < NC) av[buf][lane] = a;
        }
        __syncwarp();

        // logZ2 = offe + log2(sum_j a_j * endx_j)
        float ex = (lane < NC) ? a * endx : 0.f;
#pragma unroll
        for (int d = 16; d > 0; d >>= 1)
            ex += __shfl_xor_sync(0xffffffffu, ex, d);
        if (lane == 0)
            g_res[b] = (float)offe + fast_lg2(ex) - s_num2;
    }
#undef LAB
}

// ---------------------------------------------------------------------------
// Kernel 3: deterministic final reduction -> loss = mean(logZ - num)
// ---------------------------------------------------------------------------
__global__ void finish_kernel(float* __restrict__ out) {
    int tid = threadIdx.x;           // 32 threads
    float v = g_res[tid] + g_res[tid + 32];
#pragma unroll
    for (int d = 16; d > 0; d >>= 1)
        v += __shfl_xor_sync(0xffffffffu, v, d);
    if (tid == 0) out[0] = v * (1.0f / (64.0f * L2E));
}

// ---------------------------------------------------------------------------
// Size-based input resolution; the three 21-vectors in encounter order are
// (bias, start, end).
// ---------------------------------------------------------------------------
extern "C" void kernel_launch(void* const* d_in, const int* in_sizes, int n_in,
                              void* d_out, int out_size)
{
    const float* hidden = nullptr;
    const float* W      = nullptr;
    const float* trans  = nullptr;
    const int*   labels = nullptr;
    const float* small[3] = {nullptr, nullptr, nullptr};
    int nsmall = 0;

    for (int i = 0; i < n_in; i++) {
        switch (in_sizes[i]) {
            case BATCH * SEQ * HID: hidden = (const float*)d_in[i]; break;
            case HID * NC:          W      = (const float*)d_in[i]; break;
            case NC * NC:           trans  = (const float*)d_in[i]; break;
            case BATCH * SEQ:       labels = (const int*)d_in[i];   break;
            case NC: if (nsmall < 3) small[nsmall++] = (const float*)d_in[i]; break;
            default: break;
        }
    }
    const float* bias    = small[0];
    const float* start_t = small[1];
    const float* end_t   = small[2];

    gemm_kernel<<<512, 256>>>(hidden, W, bias);
    crf_kernel<<<BATCH, 128>>>(start_t, end_t, trans, labels);
    finish_kernel<<<1, 32>>>((float*)d_out);
}

// round 6
// speedup vs baseline: 2.1538x; 1.1697x over previous
#include <cuda_runtime.h>
#include <cstdint>

#define L2E 1.4426950408889634f
#define BATCH 64
#define SEQ 512
#define HID 768
#define NC 21
#define EM_STRIDE (SEQ * NC)   // 10752 floats per batch

__device__ __align__(16) float g_em2[BATCH * SEQ * NC];  // log2-scaled emissions
__device__ __align__(16) float g_emx[BATCH * SEQ * NC];  // 2^em2 (linear)
__device__ float g_res[BATCH];                           // per-batch (logZ2 - num2)

__device__ __forceinline__ float fast_ex2(float x) {
    float y; asm("ex2.approx.ftz.f32 %0, %1;" : "=f"(y) : "f"(x)); return y;
}
__device__ __forceinline__ float fast_lg2(float x) {
    float y; asm("lg2.approx.ftz.f32 %0, %1;" : "=f"(y) : "f"(x)); return y;
}
__device__ __forceinline__ void cp_async4(void* smem_dst, const void* gmem_src) {
    unsigned d = (unsigned)__cvta_generic_to_shared(smem_dst);
    asm volatile("cp.async.ca.shared.global [%0], [%1], 4;" :: "r"(d), "l"(gmem_src));
}
__device__ __forceinline__ void cp_commit() {
    asm volatile("cp.async.commit_group;");
}
#define FFMA2(acc, a, b) \
    asm("fma.rn.f32x2 %0, %1, %2, %3;" : "=l"(acc) : "l"(a), "l"(b), "l"(acc))

// ---------------------------------------------------------------------------
// Kernel 1: emissions GEMM. Key change vs R5: 2 output rows per thread so the
// 3 broadcast ws LDS.128 feed 12 FFMA2 (was 6) -> smem wavefronts per FLOP
// halve (crossbar was the binding pipe: L1=63%). 2-stage cp.async pipeline.
// 512 blocks x 256 threads, BM=64, BK=32.
// thread = (m2 = tid&31 -> rows {m2, m2+32}, half = (tid>>5)&1 -> 12 cols,
//           ks = tid>>6 -> 8 of 32 kk). 4-way K-split merged via smem.
// ---------------------------------------------------------------------------
__global__ __launch_bounds__(256) void gemm_kernel(
    const float* __restrict__ hidden,
    const float* __restrict__ W,
    const float* __restrict__ bias)
{
    __shared__ __align__(16) float hs[2][64][33];        // 16896 B, stride 33: conflict-free
    __shared__ __align__(16) float ws[2][32][24];        // 6144 B, pad->24 (16B rows)
    __shared__ __align__(16) uint64_t mrg[64][3][12];    // 18432 B merge

    const int tid  = threadIdx.x;
    const int m2   = tid & 31;
    const int half = (tid >> 5) & 1;
    const int ks   = tid >> 6;           // 0..3
    const int grp  = tid & 63;
    const int row0 = blockIdx.x * 64;

    // zero ws pad columns (cols 21..23, read by half==1 FFMA2 lanes)
    if (tid < 192) {
        int s = tid / 96, rem = tid % 96;
        ws[s][rem / 3][21 + rem % 3] = 0.f;
    }

    auto issue = [&](int k0, int s) {
#pragma unroll
        for (int u = 0; u < 8; u++) {                 // 2048 floats / 256 thr
            int idx = tid + u * 256;
            int r = idx >> 5, kk = idx & 31;
            cp_async4(&hs[s][r][kk], &hidden[(row0 + r) * HID + k0 + kk]);
        }
#pragma unroll
        for (int u = 0; u < 3; u++) {                 // 672 floats
            int idx = tid + u * 256;
            if (idx < 32 * NC) {
                int kk = idx / NC, c = idx - kk * NC;
                cp_async4(&ws[s][kk][c], &W[(k0 + kk) * NC + c]);
            }
        }
    };

    uint64_t acc[2][6];
#pragma unroll
    for (int r = 0; r < 2; r++)
#pragma unroll
        for (int i = 0; i < 6; i++) acc[r][i] = 0ull;

    issue(0, 0); cp_commit();

    const int NK = HID / 32;   // 24
    const int kklo = ks * 8;
    for (int k = 0; k < NK; k++) {
        if (k + 1 < NK) { issue((k + 1) * 32, (k + 1) & 1); cp_commit(); }
        if (k + 1 < NK) asm volatile("cp.async.wait_group 1;");
        else            asm volatile("cp.async.wait_group 0;");
        __syncthreads();

        const int s = k & 1;
#pragma unroll
        for (int kk = kklo; kk < kklo + 8; kk++) {
            float h0 = hs[s][m2][kk];
            float h1 = hs[s][m2 + 32][kk];
            uint64_t h0x, h1x;
            asm("mov.b64 %0, {%1, %1};" : "=l"(h0x) : "f"(h0));
            asm("mov.b64 %0, {%1, %1};" : "=l"(h1x) : "f"(h1));
            const ulonglong2* wp =
                reinterpret_cast<const ulonglong2*>(&ws[s][kk][half * 12]);
            ulonglong2 q0 = wp[0], q1 = wp[1], q2 = wp[2];
            FFMA2(acc[0][0], h0x, q0.x); FFMA2(acc[0][1], h0x, q0.y);
            FFMA2(acc[0][2], h0x, q1.x); FFMA2(acc[0][3], h0x, q1.y);
            FFMA2(acc[0][4], h0x, q2.x); FFMA2(acc[0][5], h0x, q2.y);
            FFMA2(acc[1][0], h1x, q0.x); FFMA2(acc[1][1], h1x, q0.y);
            FFMA2(acc[1][2], h1x, q1.x); FFMA2(acc[1][3], h1x, q1.y);
            FFMA2(acc[1][4], h1x, q2.x); FFMA2(acc[1][5], h1x, q2.y);
        }
        __syncthreads();
    }

    // merge 4-way K-split partials, apply bias, write em2 + emx
    if (ks != 0) {
#pragma unroll
        for (int r = 0; r < 2; r++)
#pragma unroll
            for (int i = 0; i < 6; i++) mrg[grp][ks - 1][r * 6 + i] = acc[r][i];
    }
    __syncthreads();
    if (ks == 0) {
        const int cb = half * 12;
#pragma unroll
        for (int r = 0; r < 2; r++) {
            const int out_base = (row0 + m2 + r * 32) * NC;
#pragma unroll
            for (int p = 0; p < 6; p++) {
                uint64_t sum = acc[r][p];
#pragma unroll
                for (int q = 0; q < 3; q++) {
                    uint64_t o = mrg[grp][q][r * 6 + p];
                    asm("add.rn.f32x2 %0, %1, %2;" : "=l"(sum) : "l"(sum), "l"(o));
                }
                float2 f = *reinterpret_cast<float2*>(&sum);
                int c = cb + 2 * p;
                if (c < NC) {
                    float v = (f.x + bias[c]) * L2E;
                    g_em2[out_base + c] = v;
                    g_emx[out_base + c] = fast_ex2(v);
                }
                if (c + 1 < NC) {
                    float v = (f.y + bias[c + 1]) * L2E;
                    g_em2[out_base + c + 1] = v;
                    g_emx[out_base + c + 1] = fast_ex2(v);
                }
            }
        }
    }
}

// ---------------------------------------------------------------------------
// Kernel 2: per-batch CRF, linear-space scan, smem-broadcast alpha.
// R6: 6 partial FMA chains (dep chain 32->16 cyc) and renorm scale folded
// into the emission multiply off the critical path.
// ---------------------------------------------------------------------------
__global__ __launch_bounds__(128) void crf_kernel(
    const float* __restrict__ start_t,
    const float* __restrict__ end_t,
    const float* __restrict__ trans,
    const int*   __restrict__ labr)
{
    __shared__ __align__(16) float emx_s[SEQ * NC];  // 43008 B
    __shared__ __align__(16) float av[2][24];
    __shared__ float red_f[128];
    __shared__ int   red_i[128];
    __shared__ float s_num2;
    __shared__ int   s_len;

    const int b   = blockIdx.x;
    const int tid = threadIdx.x;
    const float* em_g  = g_em2 + b * EM_STRIDE;
    const float* emx_g = g_emx + b * EM_STRIDE;

    // labels dtype detection (int32 vs int64; reads in-bounds for both)
    int ok = 1;
    for (int t = tid; t < SEQ; t += 128) {
        int v = labr[2 * t + 1];
        if (v != 0 && v != -1) ok = 0;
    }
    int is64 = __syncthreads_and(ok);
    const int lbase = is64 ? b * SEQ * 2 : b * SEQ;
    const int lstep = is64 ? 2 : 1;
#define LAB(t) labr[lbase + (t) * lstep]

    for (int i = tid; i < (SEQ * NC) / 4; i += 128)
        reinterpret_cast<float4*>(emx_s)[i] =
            reinterpret_cast<const float4*>(emx_g)[i];

    // numerator (log2 domain) + valid length (mask is a prefix)
    float p = 0.f;
    int cnt = 0;
    for (int t = tid; t < SEQ; t += 128) {
        int l = LAB(t);
        if (l != -100) {
            cnt++;
            if (t == 0) {
                p += start_t[l] * L2E + em_g[l];
            } else {
                int lp = LAB(t - 1);
                p += em_g[t * NC + l] + trans[lp * NC + l] * L2E;
            }
        }
    }
    red_f[tid] = p;
    red_i[tid] = cnt;
    __syncthreads();
    for (int s = 64; s > 0; s >>= 1) {
        if (tid < s) { red_f[tid] += red_f[tid + s]; red_i[tid] += red_i[tid + s]; }
        __syncthreads();
    }
    if (tid == 0) {
        int len = red_i[0];
        s_len   = len;
        s_num2  = red_f[0] + end_t[LAB(len - 1)] * L2E;
    }
    __syncthreads();

    if (tid < 32) {
        const int lane = tid;
        const int j = lane < NC ? lane : NC - 1;
        float tl[24];
#pragma unroll
        for (int i = 0; i < NC; i++) tl[i] = fast_ex2(trans[i * NC + j] * L2E);
        tl[21] = tl[22] = tl[23] = 0.f;
        const float endx = fast_ex2(end_t[j] * L2E);

        float a = fast_ex2(start_t[j] * L2E) * emx_s[j];
        if (lane < NC)  av[0][lane] = a;
        if (lane >= NC && lane < 24) { av[0][lane] = 0.f; av[1][lane] = 0.f; }
        int offe = 0;
        int buf  = 0;
        const int len = s_len;

        for (int t = 1; t < len; t++) {
            __syncwarp();
            const float4* vp = reinterpret_cast<const float4*>(av[buf]);
            float4 v0 = vp[0], v1 = vp[1], v2 = vp[2],
                   v3 = vp[3], v4 = vp[4], v5 = vp[5];
            float emn = emx_s[t * NC + j];
            // renorm scale (exact pow2), folded into emn off the critical path
            int   e     = ((__float_as_int(v0.x) >> 23) & 255) - 127;
            float sclem = __int_as_float((127 - e) << 23) * emn;
            offe += e;

            float s0 = v0.x * tl[0],  s1 = v0.y * tl[1],  s2 = v0.z * tl[2];
            float s3 = v0.w * tl[3],  s4 = v1.x * tl[4],  s5 = v1.y * tl[5];
            s0 += v1.z * tl[6];   s1 += v1.w * tl[7];   s2 += v2.x * tl[8];
            s3 += v2.y * tl[9];   s4 += v2.z * tl[10];  s5 += v2.w * tl[11];
            s0 += v3.x * tl[12];  s1 += v3.y * tl[13];  s2 += v3.z * tl[14];
            s3 += v3.w * tl[15];  s4 += v4.x * tl[16];  s5 += v4.y * tl[17];
            s0 += v4.z * tl[18];  s1 += v4.w * tl[19];  s2 += v5.x * tl[20];
            s3 += v5.y * tl[21];  s4 += v5.z * tl[22];  s5 += v5.w * tl[23];

            a = (((s0 + s1) + (s2 + s3)) + (s4 + s5)) * sclem;
            buf ^= 1;
            if (lane < NC) av[buf][lane] = a;
        }
        __syncwarp();

        float ex = (lane < NC) ? a * endx : 0.f;
#pragma unroll
        for (int d = 16; d > 0; d >>= 1)
            ex += __shfl_xor_sync(0xffffffffu, ex, d);
        if (lane == 0)
            g_res[b] = (float)offe + fast_lg2(ex) - s_num2;
    }
#undef LAB
}

// ---------------------------------------------------------------------------
__global__ void finish_kernel(float* __restrict__ out) {
    int tid = threadIdx.x;           // 32 threads
    float v = g_res[tid] + g_res[tid + 32];
#pragma unroll
    for (int d = 16; d > 0; d >>= 1)
        v += __shfl_xor_sync(0xffffffffu, v, d);
    if (tid == 0) out[0] = v * (1.0f / (64.0f * L2E));
}

// ---------------------------------------------------------------------------
extern "C" void kernel_launch(void* const* d_in, const int* in_sizes, int n_in,
                              void* d_out, int out_size)
{
    const float* hidden = nullptr;
    const float* W      = nullptr;
    const float* trans  = nullptr;
    const int*   labels = nullptr;
    const float* small[3] = {nullptr, nullptr, nullptr};
    int nsmall = 0;

    for (int i = 0; i < n_in; i++) {
        switch (in_sizes[i]) {
            case BATCH * SEQ * HID: hidden = (const float*)d_in[i]; break;
            case HID * NC:          W      = (const float*)d_in[i]; break;
            case NC * NC:           trans  = (const float*)d_in[i]; break;
            case BATCH * SEQ:       labels = (const int*)d_in[i];   break;
            case NC: if (nsmall < 3) small[nsmall++] = (const float*)d_in[i]; break;
            default: break;
        }
    }
    const float* bias    = small[0];
    const float* start_t = small[1];
    const float* end_t   = small[2];

    gemm_kernel<<<512, 256>>>(hidden, W, bias);
    crf_kernel<<<BATCH, 128>>>(start_t, end_t, trans, labels);
    finish_kernel<<<1, 32>>>((float*)d_out);
}